// round 12
// baseline (speedup 1.0000x reference)
#include <cuda_runtime.h>
#include <cuda_bf16.h>
#include <cuda_fp16.h>
#include <cstdint>

#define Bb 2
#define Ss 2048
#define Dd 1024
#define Hh 16
#define DHh 64
#define NBb 32
#define MLPD 4096
#define BS (Bb*Ss)          // 4096
#define DA 96               // augmented attention dim (64 + 32)
#define LN_EPS 1e-6f
#define LOG2E_over8 0.18033688f
#define LOG2E_tenth 0.14426950f

// ===================== helpers =============================================
__device__ __forceinline__ uint32_t smem_u32(const void* p) {
    uint32_t a;
    asm("{ .reg .u64 t; cvta.to.shared.u64 t, %1; cvt.u32.u64 %0, t; }" : "=r"(a) : "l"(p));
    return a;
}
#define LDSM_X4(r, addr) \
    asm volatile("ldmatrix.sync.aligned.m8n8.x4.shared.b16 {%0,%1,%2,%3}, [%4];" \
        : "=r"((r)[0]), "=r"((r)[1]), "=r"((r)[2]), "=r"((r)[3]) : "r"(addr))
#define LDSM_X4T(r, addr) \
    asm volatile("ldmatrix.sync.aligned.m8n8.x4.trans.shared.b16 {%0,%1,%2,%3}, [%4];" \
        : "=r"((r)[0]), "=r"((r)[1]), "=r"((r)[2]), "=r"((r)[3]) : "r"(addr))
#define MMA_BF16(c, a, b0, b1) \
    asm volatile("mma.sync.aligned.m16n8k16.row.col.f32.bf16.bf16.f32 " \
        "{%0,%1,%2,%3}, {%4,%5,%6,%7}, {%8,%9}, {%0,%1,%2,%3};" \
        : "+f"((c)[0]), "+f"((c)[1]), "+f"((c)[2]), "+f"((c)[3]) \
        : "r"((a)[0]), "r"((a)[1]), "r"((a)[2]), "r"((a)[3]), "r"(b0), "r"(b1))
#define MMA_F16(c, a, b0, b1) \
    asm volatile("mma.sync.aligned.m16n8k16.row.col.f32.f16.f16.f32 " \
        "{%0,%1,%2,%3}, {%4,%5,%6,%7}, {%8,%9}, {%0,%1,%2,%3};" \
        : "+f"((c)[0]), "+f"((c)[1]), "+f"((c)[2]), "+f"((c)[3]) \
        : "r"((a)[0]), "r"((a)[1]), "r"((a)[2]), "r"((a)[3]), "r"(b0), "r"(b1))

// ------------------- scratch (static device allocations) -------------------
__device__ float g_xln[BS*Dd];
__device__ float g_q  [BS*Dd];
__device__ float g_k  [BS*Dd];
__device__ float g_v  [BS*Dd];
__device__ float g_qb [BS*Hh*NBb];
__device__ float g_kb [BS*Hh*NBb];
__device__ float g_AO [BS*Dd];
__device__ float g_x1 [BS*Dd];
__device__ float g_yln[BS*Dd];
__device__ float g_h1 [(long)BS*MLPD];
__device__ float g_bsum[2*Hh*NBb];
// fp16 attention operands
__device__ __half g_QAh[(long)Bb*Hh*Ss*DA];
__device__ __half g_QAl[(long)Bb*Hh*Ss*DA];
__device__ __half g_KTh[(long)Bb*Hh*DA*Ss];
__device__ __half g_KTl[(long)Bb*Hh*DA*Ss];
__device__ __half g_Vh [(long)Bb*Hh*Ss*DHh];

// ------------------------------- LayerNorm ---------------------------------
__global__ void ln_kernel(const float* __restrict__ x, const float* __restrict__ g,
                          const float* __restrict__ bt, float* __restrict__ out)
{
    int row = blockIdx.x;
    int tid = threadIdx.x;                     // 256 threads, D/4 = 256 float4
    const float4* xr = (const float4*)(x + (long)row*Dd);
    float4 v = xr[tid];
    float s  = v.x+v.y+v.z+v.w;
    float s2 = v.x*v.x+v.y*v.y+v.z*v.z+v.w*v.w;
    __shared__ float sh[16];
    #pragma unroll
    for (int off=16; off; off>>=1) {
        s  += __shfl_xor_sync(0xffffffffu, s,  off);
        s2 += __shfl_xor_sync(0xffffffffu, s2, off);
    }
    int wid = tid >> 5;
    if ((tid & 31) == 0) { sh[wid] = s; sh[8+wid] = s2; }
    __syncthreads();
    if (tid < 32) {
        float a  = (tid < 8) ? sh[tid]   : 0.f;
        float b2 = (tid < 8) ? sh[8+tid] : 0.f;
        #pragma unroll
        for (int off=4; off; off>>=1) {
            a  += __shfl_xor_sync(0xffffffffu, a,  off);
            b2 += __shfl_xor_sync(0xffffffffu, b2, off);
        }
        if (tid == 0) { sh[0] = a; sh[1] = b2; }
    }
    __syncthreads();
    float mu  = sh[0] * (1.f/Dd);
    float var = sh[1] * (1.f/Dd) - mu*mu;
    float inv = rsqrtf(var + LN_EPS);
    float4 gg = ((const float4*)g)[tid];
    float4 bb = ((const float4*)bt)[tid];
    float4 r;
    r.x = (v.x-mu)*inv*gg.x + bb.x;
    r.y = (v.y-mu)*inv*gg.y + bb.y;
    r.z = (v.z-mu)*inv*gg.z + bb.z;
    r.w = (v.w-mu)*inv*gg.w + bb.w;
    ((float4*)(out + (long)row*Dd))[tid] = r;
}

// ==================== bf16x3 mma.sync GEMM (128M x 256N CTA) ===============
// 8 warps in 2(m) x 4(n); warp tile 64x64 -> 85 B LDSM per HMMA
#define SWA 40      // A smem row stride (halfs)
#define SWB 264     // B smem row stride (halfs) for 256 cols (528B; 528%128=16 -> LDSM-T conflict-free)
#define ASTG (128*SWA)      // 5120 halfs / plane / stage
#define BSTG (32*SWB)       // 8448 halfs / plane / stage
#define GEMM_SMEM ((2*ASTG*2 + 2*BSTG*2) * 2)   // 108544 bytes

__device__ __forceinline__ void split_sts(const float* p,
                                          __nv_bfloat16* hiDst, __nv_bfloat16* loDst)
{
    __align__(16) __nv_bfloat16 hh[16], ll[16];
    #pragma unroll
    for (int i = 0; i < 16; i++) {
        float x = p[i];
        __nv_bfloat16 h = __float2bfloat16_rn(x);
        hh[i] = h;
        ll[i] = __float2bfloat16_rn(x - __bfloat162float(h));
    }
    ((uint4*)hiDst)[0] = ((uint4*)hh)[0];
    ((uint4*)hiDst)[1] = ((uint4*)hh)[1];
    ((uint4*)loDst)[0] = ((uint4*)ll)[0];
    ((uint4*)loDst)[1] = ((uint4*)ll)[1];
}

__global__ __launch_bounds__(256, 1)
void gemm_mma(const float* __restrict__ A, const float* __restrict__ Bw,
              float* __restrict__ C, int M, int N, int K,
              const float* __restrict__ bias, const float* __restrict__ res, int relu)
{
    extern __shared__ __nv_bfloat16 smh[];
    __nv_bfloat16* sAh = smh;                    // [2][ASTG]
    __nv_bfloat16* sAl = smh + 2*ASTG;           // [2][ASTG]
    __nv_bfloat16* sBh = smh + 4*ASTG;           // [2][BSTG]
    __nv_bfloat16* sBl = smh + 4*ASTG + 2*BSTG;  // [2][BSTG]
    const uint32_t smbase = smem_u32(smh);

    const int tid  = threadIdx.x;
    const int lane = tid & 31;
    const int wid  = tid >> 5;
    const int m0 = blockIdx.y * 128, n0 = blockIdx.x * 256;
    const int m0w = (wid & 1) * 64, n0w = (wid >> 1) * 64;

    // producer mapping
    const int arow = tid >> 1, akh = (tid & 1) * 16;      // A: 128 rows x 2 half-rows
    const int bkr  = tid >> 3, bns = (tid & 7) * 32;      // B: 32 k-rows x 8 segs of 32
    const float* Ag0 = A  + (long)(m0 + arow)*K + akh;
    const float* Bg0 = Bw + (long)bkr*N + n0 + bns;

    float acc[4][8][4];
    #pragma unroll
    for (int i=0;i<4;i++)
        #pragma unroll
        for (int j=0;j<8;j++)
            #pragma unroll
            for (int t=0;t<4;t++) acc[i][j][t] = 0.f;

    const int KC = K >> 5;
    float pa[16], pb[32];

    // chunk 0
    #pragma unroll
    for (int i=0;i<4;i++) *(float4*)&pa[i*4] = *(const float4*)(Ag0 + i*4);
    #pragma unroll
    for (int i=0;i<8;i++) *(float4*)&pb[i*4] = *(const float4*)(Bg0 + i*4);
    split_sts(pa,      sAh + arow*SWA + akh,      sAl + arow*SWA + akh);
    split_sts(pb,      sBh + bkr*SWB + bns,       sBl + bkr*SWB + bns);
    split_sts(pb + 16, sBh + bkr*SWB + bns + 16,  sBl + bkr*SWB + bns + 16);
    __syncthreads();

    // ldmatrix lane mapping
    const int arow_l = (lane & 15);
    const int acol_l = (lane >> 4) << 3;
    const int bkr_l  = ((lane >> 3) & 1) * 8 + (lane & 7);
    const int bnc_l  = n0w + ((lane >> 4) << 3);

    for (int c = 0; c < KC; c++) {
        const int st = c & 1;
        // LDG of chunk c+1 (issued early; consumed by STS after MMA phase)
        if (c + 1 < KC) {
            const float* Agn = Ag0 + (c+1)*32;
            const float* Bgn = Bg0 + (long)(c+1)*32*N;
            #pragma unroll
            for (int i=0;i<4;i++) *(float4*)&pa[i*4] = *(const float4*)(Agn + i*4);
            #pragma unroll
            for (int i=0;i<8;i++) *(float4*)&pb[i*4] = *(const float4*)(Bgn + i*4);
        }

        const uint32_t baseAh = smbase + (uint32_t)(st*ASTG)*2;
        const uint32_t baseAl = baseAh + (uint32_t)(2*ASTG)*2;
        const uint32_t baseBh = smbase + (uint32_t)(4*ASTG + st*BSTG)*2;
        const uint32_t baseBl = baseBh + (uint32_t)(2*BSTG)*2;

        #pragma unroll
        for (int ks = 0; ks < 2; ks++) {
            const int kst = ks*16;
            // load all B fragments for this k16 (reused across 4 m-tiles)
            uint32_t bh[4][4], bl[4][4];
            #pragma unroll
            for (int ntp = 0; ntp < 4; ntp++) {
                uint32_t boff = (uint32_t)((kst + bkr_l)*SWB + bnc_l + ntp*16)*2;
                LDSM_X4T(bh[ntp], baseBh + boff);
                LDSM_X4T(bl[ntp], baseBl + boff);
            }
            #pragma unroll
            for (int mt = 0; mt < 4; mt++) {
                uint32_t ah[4], al[4];
                uint32_t aoff = (uint32_t)((m0w + mt*16 + arow_l)*SWA + kst + acol_l)*2;
                LDSM_X4(ah, baseAh + aoff);
                LDSM_X4(al, baseAl + aoff);
                #pragma unroll
                for (int ntp = 0; ntp < 4; ntp++) {
                    MMA_BF16(acc[mt][2*ntp],   ah, bh[ntp][0], bh[ntp][1]);
                    MMA_BF16(acc[mt][2*ntp],   ah, bl[ntp][0], bl[ntp][1]);
                    MMA_BF16(acc[mt][2*ntp],   al, bh[ntp][0], bh[ntp][1]);
                    MMA_BF16(acc[mt][2*ntp+1], ah, bh[ntp][2], bh[ntp][3]);
                    MMA_BF16(acc[mt][2*ntp+1], ah, bl[ntp][2], bl[ntp][3]);
                    MMA_BF16(acc[mt][2*ntp+1], al, bh[ntp][2], bh[ntp][3]);
                }
            }
        }

        if (c + 1 < KC) {
            const int s2 = st ^ 1;
            split_sts(pa,      sAh + s2*ASTG + arow*SWA + akh,     sAl + s2*ASTG + arow*SWA + akh);
            split_sts(pb,      sBh + s2*BSTG + bkr*SWB + bns,      sBl + s2*BSTG + bkr*SWB + bns);
            split_sts(pb + 16, sBh + s2*BSTG + bkr*SWB + bns + 16, sBl + s2*BSTG + bkr*SWB + bns + 16);
        }
        __syncthreads();
    }

    // epilogue
    const int gid = lane >> 2, tig = lane & 3;
    #pragma unroll
    for (int mt = 0; mt < 4; mt++) {
        #pragma unroll
        for (int nt = 0; nt < 8; nt++) {
            long row = m0 + m0w + mt*16 + gid;
            int  col = n0 + n0w + nt*8 + tig*2;
            float2 v0 = make_float2(acc[mt][nt][0], acc[mt][nt][1]);
            float2 v1 = make_float2(acc[mt][nt][2], acc[mt][nt][3]);
            if (bias) {
                float2 bv = *(const float2*)&bias[col];
                v0.x += bv.x; v0.y += bv.y; v1.x += bv.x; v1.y += bv.y;
            }
            if (relu) {
                v0.x = fmaxf(v0.x, 0.f); v0.y = fmaxf(v0.y, 0.f);
                v1.x = fmaxf(v1.x, 0.f); v1.y = fmaxf(v1.y, 0.f);
            }
            if (res) {
                float2 r0 = *(const float2*)&res[row*N + col];
                float2 r1 = *(const float2*)&res[(row+8)*N + col];
                v0.x += r0.x; v0.y += r0.y; v1.x += r1.x; v1.y += r1.y;
            }
            *(float2*)&C[row*N + col]     = v0;
            *(float2*)&C[(row+8)*N + col] = v1;
        }
    }
}

// ------------------------- bucket softmax (qb / kb) -------------------------
__global__ void bucket_kernel(const float* __restrict__ qk, const float* __restrict__ Wh,
                              float* __restrict__ out)
{
    int gw   = blockIdx.x * (blockDim.x >> 5) + (threadIdx.x >> 5);
    int lane = threadIdx.x & 31;
    if (gw >= BS*Hh) return;
    int h  = gw % Hh;
    int bs = gw / Hh;
    const float* qrow = qk + (long)bs*Dd + h*DHh;
    const float* W    = Wh + (long)h*DHh*NBb;
    float acc = 0.f;
    #pragma unroll
    for (int f=0; f<DHh; f++) acc += qrow[f] * W[f*NBb + lane];
    float m = acc;
    #pragma unroll
    for (int off=16; off; off>>=1) m = fmaxf(m, __shfl_xor_sync(0xffffffffu, m, off));
    float e = __expf(acc - m);
    float s = e;
    #pragma unroll
    for (int off=16; off; off>>=1) s += __shfl_xor_sync(0xffffffffu, s, off);
    out[(long)gw*NBb + lane] = e / s;
}

// ------------------ prep: fp16 hi/lo attention operands ---------------------
__global__ void prep_qa(const float* __restrict__ q, const float* __restrict__ qb,
                        __half* __restrict__ QAh, __half* __restrict__ QAl)
{
    long i = (long)blockIdx.x*256 + threadIdx.x;
    const long total = (long)Bb*Hh*Ss*DA;
    if (i >= total) return;
    int  j  = (int)(i % DA);
    long r  = i / DA;
    int  s  = (int)(r % Ss);
    int  bh = (int)(r / Ss);
    int  h  = bh & 15, b = bh >> 4;
    float val = (j < DHh)
        ? q[((long)(b*Ss + s))*Dd + h*DHh + j] * LOG2E_over8
        : qb[(((long)(b*Ss + s))*Hh + h)*NBb + j - DHh] * LOG2E_tenth;
    __half hi = __float2half_rn(val);
    __half lo = __float2half_rn(val - __half2float(hi));
    QAh[i] = hi; QAl[i] = lo;
}

__global__ void prep_kt(const float* __restrict__ k, const float* __restrict__ kb,
                        __half* __restrict__ KTh, __half* __restrict__ KTl)
{
    __shared__ float t[32][33];
    int bh = blockIdx.z, b = bh >> 4, h = bh & 15;
    int j0 = blockIdx.y*32, s0 = blockIdx.x*32;
    int tx = threadIdx.x & 31, ty = threadIdx.x >> 5;
    #pragma unroll
    for (int i = 0; i < 32; i += 8) {
        int s = s0 + ty + i;
        float val = (j0 < DHh)
            ? k[((long)(b*Ss + s))*Dd + h*DHh + j0 + tx]
            : kb[(((long)(b*Ss + s))*Hh + h)*NBb + (j0 - DHh) + tx];
        t[ty+i][tx] = val;
    }
    __syncthreads();
    #pragma unroll
    for (int i = 0; i < 32; i += 8) {
        int j = j0 + ty + i;
        float val = t[tx][ty+i];
        __half hi = __float2half_rn(val);
        __half lo = __float2half_rn(val - __half2float(hi));
        long o = ((long)bh*DA + j)*Ss + s0 + tx;
        KTh[o] = hi; KTl[o] = lo;
    }
}

__global__ void prep_v(const float* __restrict__ v, __half* __restrict__ Vhh)
{
    long i = (long)blockIdx.x*256 + threadIdx.x;
    const long total = (long)Bb*Hh*Ss*DHh;
    if (i >= total) return;
    int  j  = (int)(i % DHh);
    long r  = i / DHh;
    int  s  = (int)(r % Ss);
    int  bh = (int)(r / Ss);
    int  h  = bh & 15, b = bh >> 4;
    Vhh[i] = __float2half_rn(v[((long)(b*Ss + s))*Dd + h*DHh + j]);
}

// ------------------------ tensor-core flash attention -----------------------
#define SWQ 104
#define SWK 72
#define SWV 72
#define OFF_QL (128*SWQ)            // halfs
#define OFF_KH (2*128*SWQ)
#define OFF_KL (OFF_KH + DA*SWK)
#define OFF_V  (OFF_KL + DA*SWK)
#define FLASH_SMEM ((OFF_V + 64*SWV)*2)   // bytes = 90112

__global__ __launch_bounds__(256, 2)
void flash_mma(const __half* __restrict__ QAh, const __half* __restrict__ QAl,
               const __half* __restrict__ KTh, const __half* __restrict__ KTl,
               const __half* __restrict__ Vhh, float* __restrict__ AO)
{
    extern __shared__ __half smf[];
    const uint32_t sb = smem_u32(smf);
    const int tid = threadIdx.x, lane = tid & 31, wid = tid >> 5;
    const int bh = blockIdx.y, b = bh >> 4, h = bh & 15;
    const int q0 = blockIdx.x * 128;

    // stage Q tile (resident)
    {
        const __half* Qhp = QAh + ((long)bh*Ss + q0)*DA;
        const __half* Qlp = QAl + ((long)bh*Ss + q0)*DA;
        for (int i = tid; i < 128*12; i += 256) {
            int r = i/12, seg = i%12;
            *(uint4*)&smf[r*SWQ + seg*8]          = *(const uint4*)&Qhp[(long)r*DA + seg*8];
            *(uint4*)&smf[OFF_QL + r*SWQ + seg*8] = *(const uint4*)&Qlp[(long)r*DA + seg*8];
        }
    }

    float accO[8][4];
    #pragma unroll
    for (int i=0;i<8;i++) { accO[i][0]=0.f; accO[i][1]=0.f; accO[i][2]=0.f; accO[i][3]=0.f; }
    float rsum0 = 0.f, rsum1 = 0.f;

    const int wq0  = wid * 16;
    const int arow = wq0 + (lane & 15);
    const int acol = (lane >> 4) << 3;
    const int bkr  = ((lane >> 3) & 1) * 8 + (lane & 7);
    const int bnc  = (lane >> 4) << 3;
    const uint32_t qh_base = sb + (uint32_t)(arow*SWQ + acol)*2;
    const uint32_t ql_base = qh_base + (uint32_t)OFF_QL*2;

    const __half* KThp = KTh + (long)bh*DA*Ss;
    const __half* KTlp = KTl + (long)bh*DA*Ss;
    const __half* Vp   = Vhh + (long)bh*Ss*DHh;

    for (int s0 = 0; s0 < Ss; s0 += 64) {
        __syncthreads();
        // producer: K tile [96][64] hi/lo + V tile [64][64]
        for (int i = tid; i < DA*8; i += 256) {
            int r = i >> 3, seg = i & 7;
            *(uint4*)&smf[OFF_KH + r*SWK + seg*8] = *(const uint4*)&KThp[(long)r*Ss + s0 + seg*8];
            *(uint4*)&smf[OFF_KL + r*SWK + seg*8] = *(const uint4*)&KTlp[(long)r*Ss + s0 + seg*8];
        }
        for (int i = tid; i < 64*8; i += 256) {
            int r = i >> 3, seg = i & 7;
            *(uint4*)&smf[OFF_V + r*SWV + seg*8] = *(const uint4*)&Vp[(long)(s0 + r)*DHh + seg*8];
        }
        __syncthreads();

        // S = QA * KA^T (fp16 3-term, log2 domain)
        float accs[8][4];
        #pragma unroll
        for (int i=0;i<8;i++) { accs[i][0]=0.f; accs[i][1]=0.f; accs[i][2]=0.f; accs[i][3]=0.f; }
        #pragma unroll
        for (int ks = 0; ks < 6; ks++) {
            uint32_t qh[4], ql[4];
            LDSM_X4(qh, qh_base + (uint32_t)(ks*16)*2);
            LDSM_X4(ql, ql_base + (uint32_t)(ks*16)*2);
            #pragma unroll
            for (int half = 0; half < 2; half++) {
                uint32_t kh[2][4], kl[2][4];
                #pragma unroll
                for (int p = 0; p < 2; p++) {
                    int ntp = half*2 + p;
                    uint32_t off = (uint32_t)((ks*16 + bkr)*SWK + bnc + ntp*16)*2;
                    LDSM_X4T(kh[p], sb + (uint32_t)OFF_KH*2 + off);
                    LDSM_X4T(kl[p], sb + (uint32_t)OFF_KL*2 + off);
                }
                #pragma unroll
                for (int p = 0; p < 2; p++) {
                    int nt = half*2 + p;
                    MMA_F16(accs[2*nt],   qh, kh[p][0], kh[p][1]);
                    MMA_F16(accs[2*nt+1], qh, kh[p][2], kh[p][3]);
                }
                #pragma unroll
                for (int p = 0; p < 2; p++) {
                    int nt = half*2 + p;
                    MMA_F16(accs[2*nt],   qh, kl[p][0], kl[p][1]);
                    MMA_F16(accs[2*nt+1], qh, kl[p][2], kl[p][3]);
                }
                #pragma unroll
                for (int p = 0; p < 2; p++) {
                    int nt = half*2 + p;
                    MMA_F16(accs[2*nt],   ql, kh[p][0], kh[p][1]);
                    MMA_F16(accs[2*nt+1], ql, kh[p][2], kh[p][3]);
                }
            }
        }

        // P = exp2(S) in fp16 packed; rowsum over the SAME fp16 values
        uint32_t P[4][4];
        __half2 rsA = __float2half2_rn(0.f), rsB = __float2half2_rn(0.f);
        #pragma unroll
        for (int nt = 0; nt < 8; nt++) {
            __half2 p01 = h2exp2(__floats2half2_rn(accs[nt][0], accs[nt][1]));
            __half2 p23 = h2exp2(__floats2half2_rn(accs[nt][2], accs[nt][3]));
            P[nt>>1][(nt&1)*2+0] = *reinterpret_cast<uint32_t*>(&p01);
            P[nt>>1][(nt&1)*2+1] = *reinterpret_cast<uint32_t*>(&p23);
            rsA = __hadd2(rsA, p01);
            rsB = __hadd2(rsB, p23);
        }
        float sf0 = __low2float(rsA) + __high2float(rsA);
        float sf1 = __low2float(rsB) + __high2float(rsB);
        sf0 += __shfl_xor_sync(0xffffffffu, sf0, 1);
        sf0 += __shfl_xor_sync(0xffffffffu, sf0, 2);
        sf1 += __shfl_xor_sync(0xffffffffu, sf1, 1);
        sf1 += __shfl_xor_sync(0xffffffffu, sf1, 2);
        rsum0 += sf0; rsum1 += sf1;

        // O += P * V (fp16)
        #pragma unroll
        for (int kt = 0; kt < 4; kt++) {
            #pragma unroll
            for (int vtp = 0; vtp < 4; vtp++) {
                uint32_t vv[4];
                LDSM_X4T(vv, sb + (uint32_t)OFF_V*2 +
                             (uint32_t)((kt*16 + bkr)*SWV + bnc + vtp*16)*2);
                MMA_F16(accO[2*vtp],   P[kt], vv[0], vv[1]);
                MMA_F16(accO[2*vtp+1], P[kt], vv[2], vv[3]);
            }
        }
    }

    // epilogue: normalize and write AO[b][s][h*64+dh]
    const float i0 = 1.f / rsum0, i1 = 1.f / rsum1;
    const int gid = lane >> 2, tig = lane & 3;
    const long row0 = (long)(b*Ss + q0 + wq0 + gid);
    #pragma unroll
    for (int nt = 0; nt < 8; nt++) {
        int col = h*DHh + nt*8 + tig*2;
        *(float2*)&AO[row0*Dd + col]     = make_float2(accO[nt][0]*i0, accO[nt][1]*i0);
        *(float2*)&AO[(row0+8)*Dd + col] = make_float2(accO[nt][2]*i1, accO[nt][3]*i1);
    }
}

// ---------------------------- bucket load-balance loss ----------------------
__global__ void bsum_kernel(const float* __restrict__ qb, const float* __restrict__ kb,
                            float* __restrict__ bsum)
{
    int id = blockIdx.x;
    const float* src = (id < Hh*NBb) ? qb : kb;
    int hn = id % (Hh*NBb);
    float s = 0.f;
    for (int r = threadIdx.x; r < BS; r += blockDim.x)
        s += src[(long)r*(Hh*NBb) + hn];
    __shared__ float sh[8];
    #pragma unroll
    for (int off=16; off; off>>=1) s += __shfl_xor_sync(0xffffffffu, s, off);
    int wid = threadIdx.x >> 5;
    if ((threadIdx.x & 31) == 0) sh[wid] = s;
    __syncthreads();
    if (threadIdx.x < 8) {
        float a = sh[threadIdx.x];
        #pragma unroll
        for (int off=4; off; off>>=1) a += __shfl_xor_sync(0xffffffffu, a, off, 8);
        if (threadIdx.x == 0) bsum[id] = a / (float)BS;
    }
}

__global__ void loss_kernel(const float* __restrict__ bsum, float* __restrict__ out)
{
    float t = 0.f;
    for (int i = threadIdx.x; i < 2*Hh*NBb; i += blockDim.x) {
        float v = bsum[i]; t += v*v;
    }
    __shared__ float sh[8];
    #pragma unroll
    for (int off=16; off; off>>=1) t += __shfl_xor_sync(0xffffffffu, t, off);
    int wid = threadIdx.x >> 5;
    if ((threadIdx.x & 31) == 0) sh[wid] = t;
    __syncthreads();
    if (threadIdx.x == 0) {
        float tot = 0.f;
        for (int i=0;i<8;i++) tot += sh[i];
        out[(long)BS*Dd] = 0.5f * (float)NBb / (float)Hh * tot;
    }
}

// --------------------------------- launch -----------------------------------
extern "C" void kernel_launch(void* const* d_in, const int* in_sizes, int n_in,
                              void* d_out, int out_size)
{
    const float* inputs = (const float*)d_in[0];
    const float* ln1_g  = (const float*)d_in[1];
    const float* ln1_b  = (const float*)d_in[2];
    const float* Wq     = (const float*)d_in[3];
    const float* Wk     = (const float*)d_in[4];
    const float* Wv     = (const float*)d_in[5];
    const float* Whq    = (const float*)d_in[6];
    const float* Whk    = (const float*)d_in[7];
    const float* Wo     = (const float*)d_in[8];
    const float* ln2_g  = (const float*)d_in[9];
    const float* ln2_b  = (const float*)d_in[10];
    const float* W1     = (const float*)d_in[11];
    const float* b1     = (const float*)d_in[12];
    const float* W2     = (const float*)d_in[13];
    const float* b2     = (const float*)d_in[14];
    float* out = (float*)d_out;

    float *xln, *q, *k, *v, *qb, *kb, *AO, *x1, *yln, *h1, *bsum;
    __half *QAh, *QAl, *KTh, *KTl, *Vhh;
    cudaGetSymbolAddress((void**)&xln, g_xln);
    cudaGetSymbolAddress((void**)&q,   g_q);
    cudaGetSymbolAddress((void**)&k,   g_k);
    cudaGetSymbolAddress((void**)&v,   g_v);
    cudaGetSymbolAddress((void**)&qb,  g_qb);
    cudaGetSymbolAddress((void**)&kb,  g_kb);
    cudaGetSymbolAddress((void**)&AO,  g_AO);
    cudaGetSymbolAddress((void**)&x1,  g_x1);
    cudaGetSymbolAddress((void**)&yln, g_yln);
    cudaGetSymbolAddress((void**)&h1,  g_h1);
    cudaGetSymbolAddress((void**)&bsum,g_bsum);
    cudaGetSymbolAddress((void**)&QAh, g_QAh);
    cudaGetSymbolAddress((void**)&QAl, g_QAl);
    cudaGetSymbolAddress((void**)&KTh, g_KTh);
    cudaGetSymbolAddress((void**)&KTl, g_KTl);
    cudaGetSymbolAddress((void**)&Vhh, g_Vh);

    cudaFuncSetAttribute(gemm_mma, cudaFuncAttributeMaxDynamicSharedMemorySize, GEMM_SMEM);
    cudaFuncSetAttribute(flash_mma, cudaFuncAttributeMaxDynamicSharedMemorySize, FLASH_SMEM);

    // 1. LN1
    ln_kernel<<<BS, 256>>>(inputs, ln1_g, ln1_b, xln);

    // 2. QKV projections (CTA tile 128x256)
    dim3 gqkv(Dd/256, BS/128);
    gemm_mma<<<gqkv, 256, GEMM_SMEM>>>(xln, Wq, q, BS, Dd, Dd, nullptr, nullptr, 0);
    gemm_mma<<<gqkv, 256, GEMM_SMEM>>>(xln, Wk, k, BS, Dd, Dd, nullptr, nullptr, 0);
    gemm_mma<<<gqkv, 256, GEMM_SMEM>>>(xln, Wv, v, BS, Dd, Dd, nullptr, nullptr, 0);

    // 3. bucket softmaxes
    int nwarp_blocks = (BS*Hh) / 8;
    bucket_kernel<<<nwarp_blocks, 256>>>(q, Whq, qb);
    bucket_kernel<<<nwarp_blocks, 256>>>(k, Whk, kb);

    // 4. fp16 operand prep
    {
        long totA = (long)Bb*Hh*Ss*DA;
        prep_qa<<<(int)((totA + 255)/256), 256>>>(q, qb, QAh, QAl);
        prep_kt<<<dim3(Ss/32, DA/32, Bb*Hh), 256>>>(k, kb, KTh, KTl);
        long totV = (long)Bb*Hh*Ss*DHh;
        prep_v<<<(int)((totV + 255)/256), 256>>>(v, Vhh);
    }

    // 5. tensor-core flash attention
    flash_mma<<<dim3(Ss/128, Bb*Hh), 256, FLASH_SMEM>>>(QAh, QAl, KTh, KTl, Vhh, AO);

    // 6. output projection + residual -> x1
    gemm_mma<<<gqkv, 256, GEMM_SMEM>>>(AO, Wo, x1, BS, Dd, Dd, nullptr, inputs, 0);

    // 7. LN2
    ln_kernel<<<BS, 256>>>(x1, ln2_g, ln2_b, yln);

    // 8. MLP up + bias + relu
    dim3 g1(MLPD/256, BS/128);
    gemm_mma<<<g1, 256, GEMM_SMEM>>>(yln, W1, h1, BS, MLPD, Dd, b1, nullptr, 1);

    // 9. MLP down + bias + residual -> d_out
    dim3 g2(Dd/256, BS/128);
    gemm_mma<<<g2, 256, GEMM_SMEM>>>(h1, W2, out, BS, Dd, MLPD, b2, x1, 0);

    // 10/11. auxiliary bucket loss -> d_out[BS*D]
    bsum_kernel<<<2*Hh*NBb, 256>>>(qb, kb, bsum);
    loss_kernel<<<1, 256>>>(bsum, out);
}

// round 13
// speedup vs baseline: 1.2570x; 1.2570x over previous
#include <cuda_runtime.h>
#include <cuda_bf16.h>
#include <cuda_fp16.h>
#include <cstdint>

#define Bb 2
#define Ss 2048
#define Dd 1024
#define Hh 16
#define DHh 64
#define NBb 32
#define MLPD 4096
#define BS (Bb*Ss)          // 4096
#define DA 96               // augmented attention dim (64 + 32)
#define LN_EPS 1e-6f
#define LOG2E_over8 0.18033688f
#define LOG2E_tenth 0.14426950f

// ===================== helpers =============================================
__device__ __forceinline__ uint32_t smem_u32(const void* p) {
    uint32_t a;
    asm("{ .reg .u64 t; cvta.to.shared.u64 t, %1; cvt.u32.u64 %0, t; }" : "=r"(a) : "l"(p));
    return a;
}
#define LDSM_X4(r, addr) \
    asm volatile("ldmatrix.sync.aligned.m8n8.x4.shared.b16 {%0,%1,%2,%3}, [%4];" \
        : "=r"((r)[0]), "=r"((r)[1]), "=r"((r)[2]), "=r"((r)[3]) : "r"(addr))
#define LDSM_X4T(r, addr) \
    asm volatile("ldmatrix.sync.aligned.m8n8.x4.trans.shared.b16 {%0,%1,%2,%3}, [%4];" \
        : "=r"((r)[0]), "=r"((r)[1]), "=r"((r)[2]), "=r"((r)[3]) : "r"(addr))
#define MMA_BF16(c, a, b0, b1) \
    asm volatile("mma.sync.aligned.m16n8k16.row.col.f32.bf16.bf16.f32 " \
        "{%0,%1,%2,%3}, {%4,%5,%6,%7}, {%8,%9}, {%0,%1,%2,%3};" \
        : "+f"((c)[0]), "+f"((c)[1]), "+f"((c)[2]), "+f"((c)[3]) \
        : "r"((a)[0]), "r"((a)[1]), "r"((a)[2]), "r"((a)[3]), "r"(b0), "r"(b1))
#define MMA_F16(c, a, b0, b1) \
    asm volatile("mma.sync.aligned.m16n8k16.row.col.f32.f16.f16.f32 " \
        "{%0,%1,%2,%3}, {%4,%5,%6,%7}, {%8,%9}, {%0,%1,%2,%3};" \
        : "+f"((c)[0]), "+f"((c)[1]), "+f"((c)[2]), "+f"((c)[3]) \
        : "r"((a)[0]), "r"((a)[1]), "r"((a)[2]), "r"((a)[3]), "r"(b0), "r"(b1))
__device__ __forceinline__ void cp16(uint32_t dst, const void* src) {
    asm volatile("cp.async.ca.shared.global [%0], [%1], 16;" :: "r"(dst), "l"(src));
}
#define CP_COMMIT() asm volatile("cp.async.commit_group;" ::: "memory")
#define CP_WAIT2()  asm volatile("cp.async.wait_group 2;" ::: "memory")

// ------------------- scratch (static device allocations) -------------------
__device__ float g_q  [BS*Dd];
__device__ float g_k  [BS*Dd];
__device__ float g_v  [BS*Dd];
__device__ float g_qb [BS*Hh*NBb];
__device__ float g_kb [BS*Hh*NBb];
__device__ float g_x1 [BS*Dd];
__device__ float g_bsum[2*Hh*NBb];
// bf16 hi/lo GEMM operand planes
__device__ __nv_bfloat16 g_xlnh[BS*Dd], g_xlnl[BS*Dd];
__device__ __nv_bfloat16 g_ylnh[BS*Dd], g_ylnl[BS*Dd];
__device__ __nv_bfloat16 g_AOh [BS*Dd], g_AOl [BS*Dd];
__device__ __nv_bfloat16 g_h1h [(long)BS*MLPD], g_h1l [(long)BS*MLPD];
__device__ __nv_bfloat16 g_Wqh[Dd*Dd], g_Wql[Dd*Dd];
__device__ __nv_bfloat16 g_Wkh[Dd*Dd], g_Wkl[Dd*Dd];
__device__ __nv_bfloat16 g_Wvh[Dd*Dd], g_Wvl[Dd*Dd];
__device__ __nv_bfloat16 g_Woh[Dd*Dd], g_Wol[Dd*Dd];
__device__ __nv_bfloat16 g_W1h[(long)Dd*MLPD], g_W1l[(long)Dd*MLPD];
__device__ __nv_bfloat16 g_W2h[(long)Dd*MLPD], g_W2l[(long)Dd*MLPD];
// fp16 attention operands
__device__ __half g_QAh[(long)Bb*Hh*Ss*DA];
__device__ __half g_QAl[(long)Bb*Hh*Ss*DA];
__device__ __half g_KTh[(long)Bb*Hh*DA*Ss];
__device__ __half g_KTl[(long)Bb*Hh*DA*Ss];
__device__ __half g_Vh [(long)Bb*Hh*Ss*DHh];

__device__ __forceinline__ void bf16split(float x, __nv_bfloat16& h, __nv_bfloat16& l) {
    h = __float2bfloat16_rn(x);
    l = __float2bfloat16_rn(x - __bfloat162float(h));
}

// --------------------- weight split (fp32 -> bf16 hi/lo) --------------------
__global__ void wsplit_kernel(const float* __restrict__ w,
                              __nv_bfloat16* __restrict__ wh,
                              __nv_bfloat16* __restrict__ wl, int n4)
{
    long i = (long)blockIdx.x*256 + threadIdx.x;
    if (i >= n4) return;
    float4 x = ((const float4*)w)[i];
    __nv_bfloat16 h[4], l[4];
    bf16split(x.x, h[0], l[0]); bf16split(x.y, h[1], l[1]);
    bf16split(x.z, h[2], l[2]); bf16split(x.w, h[3], l[3]);
    ((uint2*)wh)[i] = *(uint2*)h;
    ((uint2*)wl)[i] = *(uint2*)l;
}

// ---------------- LayerNorm (writes bf16 hi/lo planes) ----------------------
__global__ void ln_kernel(const float* __restrict__ x, const float* __restrict__ g,
                          const float* __restrict__ bt,
                          __nv_bfloat16* __restrict__ outh,
                          __nv_bfloat16* __restrict__ outl)
{
    int row = blockIdx.x;
    int tid = threadIdx.x;                     // 256 threads, D/4 = 256 float4
    const float4* xr = (const float4*)(x + (long)row*Dd);
    float4 v = xr[tid];
    float s  = v.x+v.y+v.z+v.w;
    float s2 = v.x*v.x+v.y*v.y+v.z*v.z+v.w*v.w;
    __shared__ float sh[16];
    #pragma unroll
    for (int off=16; off; off>>=1) {
        s  += __shfl_xor_sync(0xffffffffu, s,  off);
        s2 += __shfl_xor_sync(0xffffffffu, s2, off);
    }
    int wid = tid >> 5;
    if ((tid & 31) == 0) { sh[wid] = s; sh[8+wid] = s2; }
    __syncthreads();
    if (tid < 32) {
        float a  = (tid < 8) ? sh[tid]   : 0.f;
        float b2 = (tid < 8) ? sh[8+tid] : 0.f;
        #pragma unroll
        for (int off=4; off; off>>=1) {
            a  += __shfl_xor_sync(0xffffffffu, a,  off);
            b2 += __shfl_xor_sync(0xffffffffu, b2, off);
        }
        if (tid == 0) { sh[0] = a; sh[1] = b2; }
    }
    __syncthreads();
    float mu  = sh[0] * (1.f/Dd);
    float var = sh[1] * (1.f/Dd) - mu*mu;
    float inv = rsqrtf(var + LN_EPS);
    float4 gg = ((const float4*)g)[tid];
    float4 bb = ((const float4*)bt)[tid];
    float4 r;
    r.x = (v.x-mu)*inv*gg.x + bb.x;
    r.y = (v.y-mu)*inv*gg.y + bb.y;
    r.z = (v.z-mu)*inv*gg.z + bb.z;
    r.w = (v.w-mu)*inv*gg.w + bb.w;
    __nv_bfloat16 h[4], l[4];
    bf16split(r.x, h[0], l[0]); bf16split(r.y, h[1], l[1]);
    bf16split(r.z, h[2], l[2]); bf16split(r.w, h[3], l[3]);
    ((uint2*)(outh + (long)row*Dd))[tid] = *(uint2*)h;
    ((uint2*)(outl + (long)row*Dd))[tid] = *(uint2*)l;
}

// ========== bf16x3 mma.sync GEMM, pre-split operands, 4-stage cp.async =====
// C[M,N] = (Ah+Al)[M,K] @ (Bh+Bl)[K,N] (+bias)(+relu)(+res) -> fp32 C or bf16 hi/lo
#define SWA 40      // A smem row stride (halfs)
#define SWB 136     // B smem row stride (halfs)
#define ASTG (128*SWA)                  // 5120 halfs per A plane stage
#define BSTG (32*SWB)                   // 4352 halfs per B plane stage
#define STGH (2*ASTG + 2*BSTG)          // 18944 halfs per stage
#define NSTG 4
#define GEMM_SMEM (NSTG*STGH*2)         // 151552 bytes

__global__ __launch_bounds__(256, 1)
void gemm_mma(const __nv_bfloat16* __restrict__ Ah, const __nv_bfloat16* __restrict__ Al,
              const __nv_bfloat16* __restrict__ Bh, const __nv_bfloat16* __restrict__ Bl,
              float* __restrict__ C,
              __nv_bfloat16* __restrict__ Chi, __nv_bfloat16* __restrict__ Clo,
              int M, int N, int K,
              const float* __restrict__ bias, const float* __restrict__ res, int relu)
{
    extern __shared__ __nv_bfloat16 smh[];
    const uint32_t smbase = smem_u32(smh);

    const int tid  = threadIdx.x;
    const int lane = tid & 31;
    const int wid  = tid >> 5;
    const int m0 = blockIdx.y * 128, n0 = blockIdx.x * 128;
    const int m0w = (wid & 3) * 32, n0w = (wid >> 2) * 64;

    // producer mapping (2 iterations x 4 cp16 each = 128 B/thread/chunk)
    const int ar0 = tid >> 1;               // even idx row; idx=tid+256 -> row+128? no:
    // A: 512 segs (128 rows x 4 segs of 8 halfs). idx = tid, tid+256.
    // B: 512 segs (32 rows x 16 segs).
    const int KC = K >> 5;

    float acc[2][8][4];
    #pragma unroll
    for (int i=0;i<2;i++)
        #pragma unroll
        for (int j=0;j<8;j++)
            #pragma unroll
            for (int t=0;t<4;t++) acc[i][j][t] = 0.f;

    auto issue_chunk = [&](int c) {
        const int st = c & 3;
        const uint32_t sb = smbase + (uint32_t)(st*STGH)*2;
        const long kb = (long)c*32;
        #pragma unroll
        for (int r = 0; r < 2; r++) {
            int idx  = tid + r*256;
            int arow = idx >> 2, aseg = (idx & 3)*8;
            cp16(sb + (uint32_t)(arow*SWA + aseg)*2,
                 Ah + (long)(m0+arow)*K + kb + aseg);
            cp16(sb + (uint32_t)(ASTG + arow*SWA + aseg)*2,
                 Al + (long)(m0+arow)*K + kb + aseg);
            int brow = idx >> 4, bseg = (idx & 15)*8;
            cp16(sb + (uint32_t)(2*ASTG + brow*SWB + bseg)*2,
                 Bh + (kb+brow)*N + n0 + bseg);
            cp16(sb + (uint32_t)(2*ASTG + BSTG + brow*SWB + bseg)*2,
                 Bl + (kb+brow)*N + n0 + bseg);
        }
        CP_COMMIT();
    };

    issue_chunk(0); issue_chunk(1); issue_chunk(2);

    const int arow_l = m0w + (lane & 15);
    const int acol_l = (lane >> 4) << 3;
    const int bkr_l  = ((lane >> 3) & 1) * 8 + (lane & 7);
    const int bnc_l  = n0w + ((lane >> 4) << 3);

    for (int c = 0; c < KC; c++) {
        const int st = c & 3;
        CP_WAIT2();
        __syncthreads();

        const uint32_t sb    = smbase + (uint32_t)(st*STGH)*2;
        const uint32_t baseAh = sb;
        const uint32_t baseAl = sb + (uint32_t)ASTG*2;
        const uint32_t baseBh = sb + (uint32_t)(2*ASTG)*2;
        const uint32_t baseBl = sb + (uint32_t)(2*ASTG + BSTG)*2;

        #pragma unroll
        for (int ks = 0; ks < 2; ks++) {
            const int kst = ks*16;
            uint32_t ah[2][4], al[2][4];
            {
                uint32_t a0 = baseAh + (uint32_t)(arow_l*SWA + kst + acol_l)*2;
                LDSM_X4(ah[0], a0);
                LDSM_X4(ah[1], a0 + 16*SWA*2);
                uint32_t a1 = baseAl + (uint32_t)(arow_l*SWA + kst + acol_l)*2;
                LDSM_X4(al[0], a1);
                LDSM_X4(al[1], a1 + 16*SWA*2);
            }
            #pragma unroll
            for (int ntp = 0; ntp < 4; ntp++) {
                uint32_t bh[4], bl[4];
                uint32_t boff = (uint32_t)((kst + bkr_l)*SWB + bnc_l + ntp*16)*2;
                LDSM_X4T(bh, baseBh + boff);
                LDSM_X4T(bl, baseBl + boff);
                #pragma unroll
                for (int mt = 0; mt < 2; mt++) {
                    MMA_BF16(acc[mt][2*ntp],   ah[mt], bh[0], bh[1]);
                    MMA_BF16(acc[mt][2*ntp],   ah[mt], bl[0], bl[1]);
                    MMA_BF16(acc[mt][2*ntp],   al[mt], bh[0], bh[1]);
                    MMA_BF16(acc[mt][2*ntp+1], ah[mt], bh[2], bh[3]);
                    MMA_BF16(acc[mt][2*ntp+1], ah[mt], bl[2], bl[3]);
                    MMA_BF16(acc[mt][2*ntp+1], al[mt], bh[2], bh[3]);
                }
            }
        }

        if (c + 3 < KC) issue_chunk(c + 3);   // fills stage (c+3)&3 = (c-1)&3, free since sync
    }

    // epilogue
    const int gid = lane >> 2, tig = lane & 3;
    #pragma unroll
    for (int mt = 0; mt < 2; mt++) {
        #pragma unroll
        for (int nt = 0; nt < 8; nt++) {
            long row = m0 + m0w + mt*16 + gid;
            int  col = n0 + n0w + nt*8 + tig*2;
            float2 v0 = make_float2(acc[mt][nt][0], acc[mt][nt][1]);
            float2 v1 = make_float2(acc[mt][nt][2], acc[mt][nt][3]);
            if (bias) {
                float2 bv = *(const float2*)&bias[col];
                v0.x += bv.x; v0.y += bv.y; v1.x += bv.x; v1.y += bv.y;
            }
            if (relu) {
                v0.x = fmaxf(v0.x, 0.f); v0.y = fmaxf(v0.y, 0.f);
                v1.x = fmaxf(v1.x, 0.f); v1.y = fmaxf(v1.y, 0.f);
            }
            if (res) {
                float2 r0 = *(const float2*)&res[row*N + col];
                float2 r1 = *(const float2*)&res[(row+8)*N + col];
                v0.x += r0.x; v0.y += r0.y; v1.x += r1.x; v1.y += r1.y;
            }
            if (C) {
                *(float2*)&C[row*N + col]     = v0;
                *(float2*)&C[(row+8)*N + col] = v1;
            }
            if (Chi) {
                __nv_bfloat16 h0[2], l0[2], h1[2], l1[2];
                bf16split(v0.x, h0[0], l0[0]); bf16split(v0.y, h0[1], l0[1]);
                bf16split(v1.x, h1[0], l1[0]); bf16split(v1.y, h1[1], l1[1]);
                *(uint32_t*)&Chi[row*N + col]     = *(uint32_t*)h0;
                *(uint32_t*)&Clo[row*N + col]     = *(uint32_t*)l0;
                *(uint32_t*)&Chi[(row+8)*N + col] = *(uint32_t*)h1;
                *(uint32_t*)&Clo[(row+8)*N + col] = *(uint32_t*)l1;
            }
        }
    }
}

// ------------------------- bucket softmax (qb / kb) -------------------------
__global__ void bucket_kernel(const float* __restrict__ qk, const float* __restrict__ Wh,
                              float* __restrict__ out)
{
    int gw   = blockIdx.x * (blockDim.x >> 5) + (threadIdx.x >> 5);
    int lane = threadIdx.x & 31;
    if (gw >= BS*Hh) return;
    int h  = gw % Hh;
    int bs = gw / Hh;
    const float* qrow = qk + (long)bs*Dd + h*DHh;
    const float* W    = Wh + (long)h*DHh*NBb;
    float acc = 0.f;
    #pragma unroll
    for (int f=0; f<DHh; f++) acc += qrow[f] * W[f*NBb + lane];
    float m = acc;
    #pragma unroll
    for (int off=16; off; off>>=1) m = fmaxf(m, __shfl_xor_sync(0xffffffffu, m, off));
    float e = __expf(acc - m);
    float s = e;
    #pragma unroll
    for (int off=16; off; off>>=1) s += __shfl_xor_sync(0xffffffffu, s, off);
    out[(long)gw*NBb + lane] = e / s;
}

// ------------------ prep: fp16 hi/lo attention operands ---------------------
__global__ void prep_qa(const float* __restrict__ q, const float* __restrict__ qb,
                        __half* __restrict__ QAh, __half* __restrict__ QAl)
{
    long i = (long)blockIdx.x*256 + threadIdx.x;
    const long total = (long)Bb*Hh*Ss*DA;
    if (i >= total) return;
    int  j  = (int)(i % DA);
    long r  = i / DA;
    int  s  = (int)(r % Ss);
    int  bh = (int)(r / Ss);
    int  h  = bh & 15, b = bh >> 4;
    float val = (j < DHh)
        ? q[((long)(b*Ss + s))*Dd + h*DHh + j] * LOG2E_over8
        : qb[(((long)(b*Ss + s))*Hh + h)*NBb + j - DHh] * LOG2E_tenth;
    __half hi = __float2half_rn(val);
    __half lo = __float2half_rn(val - __half2float(hi));
    QAh[i] = hi; QAl[i] = lo;
}

__global__ void prep_kt(const float* __restrict__ k, const float* __restrict__ kb,
                        __half* __restrict__ KTh, __half* __restrict__ KTl)
{
    __shared__ float t[32][33];
    int bh = blockIdx.z, b = bh >> 4, h = bh & 15;
    int j0 = blockIdx.y*32, s0 = blockIdx.x*32;
    int tx = threadIdx.x & 31, ty = threadIdx.x >> 5;
    #pragma unroll
    for (int i = 0; i < 32; i += 8) {
        int s = s0 + ty + i;
        float val = (j0 < DHh)
            ? k[((long)(b*Ss + s))*Dd + h*DHh + j0 + tx]
            : kb[(((long)(b*Ss + s))*Hh + h)*NBb + (j0 - DHh) + tx];
        t[ty+i][tx] = val;
    }
    __syncthreads();
    #pragma unroll
    for (int i = 0; i < 32; i += 8) {
        int j = j0 + ty + i;
        float val = t[tx][ty+i];
        __half hi = __float2half_rn(val);
        __half lo = __float2half_rn(val - __half2float(hi));
        long o = ((long)bh*DA + j)*Ss + s0 + tx;
        KTh[o] = hi; KTl[o] = lo;
    }
}

__global__ void prep_v(const float* __restrict__ v, __half* __restrict__ Vhh)
{
    long i = (long)blockIdx.x*256 + threadIdx.x;
    const long total = (long)Bb*Hh*Ss*DHh;
    if (i >= total) return;
    int  j  = (int)(i % DHh);
    long r  = i / DHh;
    int  s  = (int)(r % Ss);
    int  bh = (int)(r / Ss);
    int  h  = bh & 15, b = bh >> 4;
    Vhh[i] = __float2half_rn(v[((long)(b*Ss + s))*Dd + h*DHh + j]);
}

// ------------------------ tensor-core flash attention -----------------------
#define SWQ 104
#define SWK 72
#define SWV 72
#define OFF_QL (128*SWQ)            // halfs
#define OFF_KH (2*128*SWQ)
#define OFF_KL (OFF_KH + DA*SWK)
#define OFF_V  (OFF_KL + DA*SWK)
#define FLASH_SMEM ((OFF_V + 64*SWV)*2)   // bytes = 90112

__global__ __launch_bounds__(256, 2)
void flash_mma(const __half* __restrict__ QAh, const __half* __restrict__ QAl,
               const __half* __restrict__ KTh, const __half* __restrict__ KTl,
               const __half* __restrict__ Vhh,
               __nv_bfloat16* __restrict__ AOh, __nv_bfloat16* __restrict__ AOl)
{
    extern __shared__ __half smf[];
    const uint32_t sb = smem_u32(smf);
    const int tid = threadIdx.x, lane = tid & 31, wid = tid >> 5;
    const int bh = blockIdx.y, b = bh >> 4, h = bh & 15;
    const int q0 = blockIdx.x * 128;

    // stage Q tile (resident)
    {
        const __half* Qhp = QAh + ((long)bh*Ss + q0)*DA;
        const __half* Qlp = QAl + ((long)bh*Ss + q0)*DA;
        for (int i = tid; i < 128*12; i += 256) {
            int r = i/12, seg = i%12;
            *(uint4*)&smf[r*SWQ + seg*8]          = *(const uint4*)&Qhp[(long)r*DA + seg*8];
            *(uint4*)&smf[OFF_QL + r*SWQ + seg*8] = *(const uint4*)&Qlp[(long)r*DA + seg*8];
        }
    }

    float accO[8][4];
    #pragma unroll
    for (int i=0;i<8;i++) { accO[i][0]=0.f; accO[i][1]=0.f; accO[i][2]=0.f; accO[i][3]=0.f; }
    float rsum0 = 0.f, rsum1 = 0.f;

    const int wq0  = wid * 16;
    const int arow = wq0 + (lane & 15);
    const int acol = (lane >> 4) << 3;
    const int bkr  = ((lane >> 3) & 1) * 8 + (lane & 7);
    const int bnc  = (lane >> 4) << 3;
    const uint32_t qh_base = sb + (uint32_t)(arow*SWQ + acol)*2;
    const uint32_t ql_base = qh_base + (uint32_t)OFF_QL*2;

    const __half* KThp = KTh + (long)bh*DA*Ss;
    const __half* KTlp = KTl + (long)bh*DA*Ss;
    const __half* Vp   = Vhh + (long)bh*Ss*DHh;

    for (int s0 = 0; s0 < Ss; s0 += 64) {
        __syncthreads();
        for (int i = tid; i < DA*8; i += 256) {
            int r = i >> 3, seg = i & 7;
            *(uint4*)&smf[OFF_KH + r*SWK + seg*8] = *(const uint4*)&KThp[(long)r*Ss + s0 + seg*8];
            *(uint4*)&smf[OFF_KL + r*SWK + seg*8] = *(const uint4*)&KTlp[(long)r*Ss + s0 + seg*8];
        }
        for (int i = tid; i < 64*8; i += 256) {
            int r = i >> 3, seg = i & 7;
            *(uint4*)&smf[OFF_V + r*SWV + seg*8] = *(const uint4*)&Vp[(long)(s0 + r)*DHh + seg*8];
        }
        __syncthreads();

        float accs[8][4];
        #pragma unroll
        for (int i=0;i<8;i++) { accs[i][0]=0.f; accs[i][1]=0.f; accs[i][2]=0.f; accs[i][3]=0.f; }
        #pragma unroll
        for (int ks = 0; ks < 6; ks++) {
            uint32_t qh[4], ql[4];
            LDSM_X4(qh, qh_base + (uint32_t)(ks*16)*2);
            LDSM_X4(ql, ql_base + (uint32_t)(ks*16)*2);
            #pragma unroll
            for (int half = 0; half < 2; half++) {
                uint32_t kh[2][4], kl[2][4];
                #pragma unroll
                for (int p = 0; p < 2; p++) {
                    int ntp = half*2 + p;
                    uint32_t off = (uint32_t)((ks*16 + bkr)*SWK + bnc + ntp*16)*2;
                    LDSM_X4T(kh[p], sb + (uint32_t)OFF_KH*2 + off);
                    LDSM_X4T(kl[p], sb + (uint32_t)OFF_KL*2 + off);
                }
                #pragma unroll
                for (int p = 0; p < 2; p++) {
                    int nt = half*2 + p;
                    MMA_F16(accs[2*nt],   qh, kh[p][0], kh[p][1]);
                    MMA_F16(accs[2*nt+1], qh, kh[p][2], kh[p][3]);
                }
                #pragma unroll
                for (int p = 0; p < 2; p++) {
                    int nt = half*2 + p;
                    MMA_F16(accs[2*nt],   qh, kl[p][0], kl[p][1]);
                    MMA_F16(accs[2*nt+1], qh, kl[p][2], kl[p][3]);
                }
                #pragma unroll
                for (int p = 0; p < 2; p++) {
                    int nt = half*2 + p;
                    MMA_F16(accs[2*nt],   ql, kh[p][0], kh[p][1]);
                    MMA_F16(accs[2*nt+1], ql, kh[p][2], kh[p][3]);
                }
            }
        }

        uint32_t P[4][4];
        __half2 rsA = __float2half2_rn(0.f), rsB = __float2half2_rn(0.f);
        #pragma unroll
        for (int nt = 0; nt < 8; nt++) {
            __half2 p01 = h2exp2(__floats2half2_rn(accs[nt][0], accs[nt][1]));
            __half2 p23 = h2exp2(__floats2half2_rn(accs[nt][2], accs[nt][3]));
            P[nt>>1][(nt&1)*2+0] = *reinterpret_cast<uint32_t*>(&p01);
            P[nt>>1][(nt&1)*2+1] = *reinterpret_cast<uint32_t*>(&p23);
            rsA = __hadd2(rsA, p01);
            rsB = __hadd2(rsB, p23);
        }
        float sf0 = __low2float(rsA) + __high2float(rsA);
        float sf1 = __low2float(rsB) + __high2float(rsB);
        sf0 += __shfl_xor_sync(0xffffffffu, sf0, 1);
        sf0 += __shfl_xor_sync(0xffffffffu, sf0, 2);
        sf1 += __shfl_xor_sync(0xffffffffu, sf1, 1);
        sf1 += __shfl_xor_sync(0xffffffffu, sf1, 2);
        rsum0 += sf0; rsum1 += sf1;

        #pragma unroll
        for (int kt = 0; kt < 4; kt++) {
            #pragma unroll
            for (int vtp = 0; vtp < 4; vtp++) {
                uint32_t vv[4];
                LDSM_X4T(vv, sb + (uint32_t)OFF_V*2 +
                             (uint32_t)((kt*16 + bkr)*SWV + bnc + vtp*16)*2);
                MMA_F16(accO[2*vtp],   P[kt], vv[0], vv[1]);
                MMA_F16(accO[2*vtp+1], P[kt], vv[2], vv[3]);
            }
        }
    }

    // epilogue: normalize, split to bf16 hi/lo, write AO planes
    const float i0 = 1.f / rsum0, i1 = 1.f / rsum1;
    const int gid = lane >> 2, tig = lane & 3;
    const long row0 = (long)(b*Ss + q0 + wq0 + gid);
    #pragma unroll
    for (int nt = 0; nt < 8; nt++) {
        int col = h*DHh + nt*8 + tig*2;
        float a0 = accO[nt][0]*i0, a1 = accO[nt][1]*i0;
        float a2 = accO[nt][2]*i1, a3 = accO[nt][3]*i1;
        __nv_bfloat16 h0[2], l0[2], h1[2], l1[2];
        bf16split(a0, h0[0], l0[0]); bf16split(a1, h0[1], l0[1]);
        bf16split(a2, h1[0], l1[0]); bf16split(a3, h1[1], l1[1]);
        *(uint32_t*)&AOh[row0*Dd + col]     = *(uint32_t*)h0;
        *(uint32_t*)&AOl[row0*Dd + col]     = *(uint32_t*)l0;
        *(uint32_t*)&AOh[(row0+8)*Dd + col] = *(uint32_t*)h1;
        *(uint32_t*)&AOl[(row0+8)*Dd + col] = *(uint32_t*)l1;
    }
}

// ---------------------------- bucket load-balance loss ----------------------
__global__ void bsum_kernel(const float* __restrict__ qb, const float* __restrict__ kb,
                            float* __restrict__ bsum)
{
    int id = blockIdx.x;
    const float* src = (id < Hh*NBb) ? qb : kb;
    int hn = id % (Hh*NBb);
    float s = 0.f;
    for (int r = threadIdx.x; r < BS; r += blockDim.x)
        s += src[(long)r*(Hh*NBb) + hn];
    __shared__ float sh[8];
    #pragma unroll
    for (int off=16; off; off>>=1) s += __shfl_xor_sync(0xffffffffu, s, off);
    int wid = threadIdx.x >> 5;
    if ((threadIdx.x & 31) == 0) sh[wid] = s;
    __syncthreads();
    if (threadIdx.x < 8) {
        float a = sh[threadIdx.x];
        #pragma unroll
        for (int off=4; off; off>>=1) a += __shfl_xor_sync(0xffffffffu, a, off, 8);
        if (threadIdx.x == 0) bsum[id] = a / (float)BS;
    }
}

__global__ void loss_kernel(const float* __restrict__ bsum, float* __restrict__ out)
{
    float t = 0.f;
    for (int i = threadIdx.x; i < 2*Hh*NBb; i += blockDim.x) {
        float v = bsum[i]; t += v*v;
    }
    __shared__ float sh[8];
    #pragma unroll
    for (int off=16; off; off>>=1) t += __shfl_xor_sync(0xffffffffu, t, off);
    int wid = threadIdx.x >> 5;
    if ((threadIdx.x & 31) == 0) sh[wid] = t;
    __syncthreads();
    if (threadIdx.x == 0) {
        float tot = 0.f;
        for (int i=0;i<8;i++) tot += sh[i];
        out[(long)BS*Dd] = 0.5f * (float)NBb / (float)Hh * tot;
    }
}

// --------------------------------- launch -----------------------------------
extern "C" void kernel_launch(void* const* d_in, const int* in_sizes, int n_in,
                              void* d_out, int out_size)
{
    const float* inputs = (const float*)d_in[0];
    const float* ln1_g  = (const float*)d_in[1];
    const float* ln1_b  = (const float*)d_in[2];
    const float* Wq     = (const float*)d_in[3];
    const float* Wk     = (const float*)d_in[4];
    const float* Wv     = (const float*)d_in[5];
    const float* Whq    = (const float*)d_in[6];
    const float* Whk    = (const float*)d_in[7];
    const float* Wo     = (const float*)d_in[8];
    const float* ln2_g  = (const float*)d_in[9];
    const float* ln2_b  = (const float*)d_in[10];
    const float* W1     = (const float*)d_in[11];
    const float* b1     = (const float*)d_in[12];
    const float* W2     = (const float*)d_in[13];
    const float* b2     = (const float*)d_in[14];
    float* out = (float*)d_out;

    float *q, *k, *v, *qb, *kb, *x1, *bsum;
    __nv_bfloat16 *xlnh, *xlnl, *ylnh, *ylnl, *AOh, *AOl, *h1h, *h1l;
    __nv_bfloat16 *Wqh, *Wql, *Wkh, *Wkl, *Wvh, *Wvl, *Woh, *Wol, *W1h, *W1l, *W2h, *W2l;
    __half *QAh, *QAl, *KTh, *KTl, *Vhh;
    cudaGetSymbolAddress((void**)&q,   g_q);
    cudaGetSymbolAddress((void**)&k,   g_k);
    cudaGetSymbolAddress((void**)&v,   g_v);
    cudaGetSymbolAddress((void**)&qb,  g_qb);
    cudaGetSymbolAddress((void**)&kb,  g_kb);
    cudaGetSymbolAddress((void**)&x1,  g_x1);
    cudaGetSymbolAddress((void**)&bsum,g_bsum);
    cudaGetSymbolAddress((void**)&xlnh, g_xlnh);  cudaGetSymbolAddress((void**)&xlnl, g_xlnl);
    cudaGetSymbolAddress((void**)&ylnh, g_ylnh);  cudaGetSymbolAddress((void**)&ylnl, g_ylnl);
    cudaGetSymbolAddress((void**)&AOh,  g_AOh);   cudaGetSymbolAddress((void**)&AOl,  g_AOl);
    cudaGetSymbolAddress((void**)&h1h,  g_h1h);   cudaGetSymbolAddress((void**)&h1l,  g_h1l);
    cudaGetSymbolAddress((void**)&Wqh,  g_Wqh);   cudaGetSymbolAddress((void**)&Wql,  g_Wql);
    cudaGetSymbolAddress((void**)&Wkh,  g_Wkh);   cudaGetSymbolAddress((void**)&Wkl,  g_Wkl);
    cudaGetSymbolAddress((void**)&Wvh,  g_Wvh);   cudaGetSymbolAddress((void**)&Wvl,  g_Wvl);
    cudaGetSymbolAddress((void**)&Woh,  g_Woh);   cudaGetSymbolAddress((void**)&Wol,  g_Wol);
    cudaGetSymbolAddress((void**)&W1h,  g_W1h);   cudaGetSymbolAddress((void**)&W1l,  g_W1l);
    cudaGetSymbolAddress((void**)&W2h,  g_W2h);   cudaGetSymbolAddress((void**)&W2l,  g_W2l);
    cudaGetSymbolAddress((void**)&QAh, g_QAh);
    cudaGetSymbolAddress((void**)&QAl, g_QAl);
    cudaGetSymbolAddress((void**)&KTh, g_KTh);
    cudaGetSymbolAddress((void**)&KTl, g_KTl);
    cudaGetSymbolAddress((void**)&Vhh, g_Vh);

    cudaFuncSetAttribute(gemm_mma, cudaFuncAttributeMaxDynamicSharedMemorySize, GEMM_SMEM);
    cudaFuncSetAttribute(flash_mma, cudaFuncAttributeMaxDynamicSharedMemorySize, FLASH_SMEM);

    // 0. weight splits (fp32 -> bf16 hi/lo)
    {
        int n4a = Dd*Dd/4, n4b = Dd*MLPD/4;
        wsplit_kernel<<<(n4a+255)/256, 256>>>(Wq, Wqh, Wql, n4a);
        wsplit_kernel<<<(n4a+255)/256, 256>>>(Wk, Wkh, Wkl, n4a);
        wsplit_kernel<<<(n4a+255)/256, 256>>>(Wv, Wvh, Wvl, n4a);
        wsplit_kernel<<<(n4a+255)/256, 256>>>(Wo, Woh, Wol, n4a);
        wsplit_kernel<<<(n4b+255)/256, 256>>>(W1, W1h, W1l, n4b);
        wsplit_kernel<<<(n4b+255)/256, 256>>>(W2, W2h, W2l, n4b);
    }

    // 1. LN1 -> bf16 hi/lo planes
    ln_kernel<<<BS, 256>>>(inputs, ln1_g, ln1_b, xlnh, xlnl);

    // 2. QKV projections -> fp32
    dim3 gqkv(Dd/128, BS/128);
    gemm_mma<<<gqkv, 256, GEMM_SMEM>>>(xlnh, xlnl, Wqh, Wql, q, nullptr, nullptr,
                                       BS, Dd, Dd, nullptr, nullptr, 0);
    gemm_mma<<<gqkv, 256, GEMM_SMEM>>>(xlnh, xlnl, Wkh, Wkl, k, nullptr, nullptr,
                                       BS, Dd, Dd, nullptr, nullptr, 0);
    gemm_mma<<<gqkv, 256, GEMM_SMEM>>>(xlnh, xlnl, Wvh, Wvl, v, nullptr, nullptr,
                                       BS, Dd, Dd, nullptr, nullptr, 0);

    // 3. bucket softmaxes
    int nwarp_blocks = (BS*Hh) / 8;
    bucket_kernel<<<nwarp_blocks, 256>>>(q, Whq, qb);
    bucket_kernel<<<nwarp_blocks, 256>>>(k, Whk, kb);

    // 4. fp16 operand prep
    {
        long totA = (long)Bb*Hh*Ss*DA;
        prep_qa<<<(int)((totA + 255)/256), 256>>>(q, qb, QAh, QAl);
        prep_kt<<<dim3(Ss/32, DA/32, Bb*Hh), 256>>>(k, kb, KTh, KTl);
        long totV = (long)Bb*Hh*Ss*DHh;
        prep_v<<<(int)((totV + 255)/256), 256>>>(v, Vhh);
    }

    // 5. tensor-core flash attention -> AO bf16 hi/lo planes
    flash_mma<<<dim3(Ss/128, Bb*Hh), 256, FLASH_SMEM>>>(QAh, QAl, KTh, KTl, Vhh, AOh, AOl);

    // 6. output projection + residual -> x1 fp32
    gemm_mma<<<gqkv, 256, GEMM_SMEM>>>(AOh, AOl, Woh, Wol, x1, nullptr, nullptr,
                                       BS, Dd, Dd, nullptr, inputs, 0);

    // 7. LN2 -> bf16 hi/lo planes
    ln_kernel<<<BS, 256>>>(x1, ln2_g, ln2_b, ylnh, ylnl);

    // 8. MLP up + bias + relu -> h1 bf16 hi/lo planes
    dim3 g1(MLPD/128, BS/128);
    gemm_mma<<<g1, 256, GEMM_SMEM>>>(ylnh, ylnl, W1h, W1l, nullptr, h1h, h1l,
                                     BS, MLPD, Dd, b1, nullptr, 1);

    // 9. MLP down + bias + residual -> d_out fp32
    dim3 g2(Dd/128, BS/128);
    gemm_mma<<<g2, 256, GEMM_SMEM>>>(h1h, h1l, W2h, W2l, out, nullptr, nullptr,
                                     BS, Dd, MLPD, b2, x1, 0);

    // 10/11. auxiliary bucket loss -> d_out[BS*D]
    bsum_kernel<<<2*Hh*NBb, 256>>>(qb, kb, bsum);
    loss_kernel<<<1, 256>>>(bsum, out);
}